// round 1
// baseline (speedup 1.0000x reference)
#include <cuda_runtime.h>
#include <math.h>

#define NN 20000
#define EE 320000
#define LL 128
#define ITERS 10

// ---------------- device scratch (no allocations allowed) ----------------
__device__ float g_x[NN * 256];      // [N][256]: cols 0..127 = z, 128..255 = h
__device__ float g_y[NN * 256];      // [N][256]: cols 0..127 = y1 = x@W1, 128..255 = y2 = x@W2
__device__ float g_agg[NN * 128];    // [N][128]
__device__ float g_a1[NN], g_a2[NN];
__device__ float g_mx[NN];
__device__ int   g_deg[NN], g_indptr[NN + 1], g_cursor[NN];
__device__ int   g_csr_src[EE], g_csr_eid[EE];

// ---------------- f32x2 packed helpers ----------------
__device__ __forceinline__ unsigned long long pk2(float x, float y) {
    unsigned long long r;
    asm("mov.b64 %0, {%1, %2};" : "=l"(r) : "f"(x), "f"(y));
    return r;
}
__device__ __forceinline__ void fma2(unsigned long long& d, unsigned long long a, unsigned long long b) {
    asm("fma.rn.f32x2 %0, %1, %2, %3;" : "=l"(d) : "l"(a), "l"(b), "l"(d));
}
__device__ __forceinline__ float2 up2(unsigned long long v) {
    float2 r;
    asm("mov.b64 {%0, %1}, %2;" : "=f"(r.x), "=f"(r.y) : "l"(v));
    return r;
}

// ---------------- init: zero deg, mx, h-part of x ----------------
__global__ void k_init() {
    int t = blockIdx.x * blockDim.x + threadIdx.x;
    if (t < NN) { g_deg[t] = 0; g_mx[t] = 0.0f; }
    if (t < NN * 128) {
        int v = t >> 7, c = t & 127;
        g_x[v * 256 + 128 + c] = 0.0f;
    }
}

__global__ void k_hist(const int* __restrict__ ei) {
    int e = blockIdx.x * blockDim.x + threadIdx.x;
    if (e >= EE) return;
    atomicAdd(&g_deg[ei[EE + e]], 1);
}

__global__ void k_scan() {
    __shared__ int sh[1024];
    int t = threadIdx.x;
    const int CH = 20;  // 1024*20 >= NN
    int base = t * CH;
    int s = 0;
    for (int i = 0; i < CH; i++) { int idx = base + i; if (idx < NN) s += g_deg[idx]; }
    sh[t] = s;
    __syncthreads();
    for (int o = 1; o < 1024; o <<= 1) {
        int v = (t >= o) ? sh[t - o] : 0;
        __syncthreads();
        sh[t] += v;
        __syncthreads();
    }
    int run = (t == 0) ? 0 : sh[t - 1];
    for (int i = 0; i < CH; i++) {
        int idx = base + i;
        if (idx < NN) { g_indptr[idx] = run; g_cursor[idx] = run; run += g_deg[idx]; }
    }
    if (t == 1023) g_indptr[NN] = sh[1023];
}

__global__ void k_scatter(const int* __restrict__ ei) {
    int e = blockIdx.x * blockDim.x + threadIdx.x;
    if (e >= EE) return;
    int d = ei[EE + e];
    int slot = atomicAdd(&g_cursor[d], 1);
    g_csr_src[slot] = ei[e];
    g_csr_eid[slot] = e;
}

// ---------------- encoder: z = relu(pos*We0 + r*We1 + be) ----------------
__global__ void k_encode(const float* __restrict__ pos, const float* __restrict__ s,
                         const float* __restrict__ Wenc, const float* __restrict__ benc,
                         int use_s) {
    int t = blockIdx.x * blockDim.x + threadIdx.x;
    if (t >= NN * 32) return;
    int v = t >> 5, c = (t & 31) << 2;
    float p = pos[v];
    float r = use_s ? s[v] : ((g_mx[v] >= 0.4f) ? 1.0f : 0.0f);
    float4 w0 = *(const float4*)(Wenc + c);
    float4 w1 = *(const float4*)(Wenc + 128 + c);
    float4 b  = *(const float4*)(benc + c);
    float4 z;
    z.x = fmaxf(fmaf(p, w0.x, fmaf(r, w1.x, b.x)), 0.0f);
    z.y = fmaxf(fmaf(p, w0.y, fmaf(r, w1.y, b.y)), 0.0f);
    z.z = fmaxf(fmaf(p, w0.z, fmaf(r, w1.z, b.z)), 0.0f);
    z.w = fmaxf(fmaf(p, w0.w, fmaf(r, w1.w, b.w)), 0.0f);
    *(float4*)(g_x + v * 256 + c) = z;
}

__global__ void k_zero_mx() {
    int t = blockIdx.x * blockDim.x + threadIdx.x;
    if (t < NN) g_mx[t] = 0.0f;
}

// ---------------- SGEMM: C[M,128(+colofs)] = A[M,K] @ B[K,128] (f32x2 FMA) ----------------
// grid.y selects B0 (colofs 0) or B1 (colofs 128). BM=128, BN=128, BK=16, 256 thr, 8x8/thread.
__global__ __launch_bounds__(256) void k_sgemm(
    const float* __restrict__ A, int lda, int M, int K,
    const float* __restrict__ B0, const float* __restrict__ B1,
    float* __restrict__ C, int ldc,
    const float* __restrict__ bias, int do_relu)
{
    __shared__ float As[16][128];
    __shared__ float Bs[16][128];
    const float* B = (blockIdx.y == 0) ? B0 : B1;
    int colofs = blockIdx.y * 128;
    int row0 = blockIdx.x * 128;
    int tid = threadIdx.x;
    int tr = tid >> 4, tc = tid & 15;

    unsigned long long acc[8][4];
#pragma unroll
    for (int i = 0; i < 8; i++)
#pragma unroll
        for (int j = 0; j < 4; j++) acc[i][j] = 0ull;

    int ar = tid >> 2;
    int ac = (tid & 3) << 2;
    int br = tid >> 5;
    int bc = (tid & 31) << 2;

    for (int k0 = 0; k0 < K; k0 += 16) {
#pragma unroll
        for (int rep = 0; rep < 2; rep++) {
            int r = ar + rep * 64;
            int grow = row0 + r;
            float4 v = make_float4(0.f, 0.f, 0.f, 0.f);
            if (grow < M) v = *(const float4*)(A + (size_t)grow * lda + k0 + ac);
            As[ac + 0][r] = v.x; As[ac + 1][r] = v.y; As[ac + 2][r] = v.z; As[ac + 3][r] = v.w;
        }
#pragma unroll
        for (int rep = 0; rep < 2; rep++) {
            int r = br + rep * 8;
            float4 v = *(const float4*)(B + (size_t)(k0 + r) * 128 + bc);
            *(float4*)(&Bs[r][bc]) = v;
        }
        __syncthreads();
#pragma unroll
        for (int kk = 0; kk < 16; kk++) {
            float4 a0 = *(const float4*)(&As[kk][tr * 8]);
            float4 a1f = *(const float4*)(&As[kk][tr * 8 + 4]);
            unsigned long long bfr[4];
#pragma unroll
            for (int j = 0; j < 4; j++)
                bfr[j] = *(const unsigned long long*)(&Bs[kk][tc * 8 + j * 2]);
            float av[8] = {a0.x, a0.y, a0.z, a0.w, a1f.x, a1f.y, a1f.z, a1f.w};
#pragma unroll
            for (int i = 0; i < 8; i++) {
                unsigned long long aa = pk2(av[i], av[i]);
#pragma unroll
                for (int j = 0; j < 4; j++) fma2(acc[i][j], aa, bfr[j]);
            }
        }
        __syncthreads();
    }
#pragma unroll
    for (int i = 0; i < 8; i++) {
        int grow = row0 + tr * 8 + i;
        if (grow >= M) continue;
#pragma unroll
        for (int j = 0; j < 4; j++) {
            float2 c = up2(acc[i][j]);
            int n = tc * 8 + j * 2;
            if (bias) { c.x += bias[n]; c.y += bias[n + 1]; }
            if (do_relu) { c.x = fmaxf(c.x, 0.0f); c.y = fmaxf(c.y, 0.0f); }
            *(float2*)(C + (size_t)grow * ldc + colofs + n) = c;
        }
    }
}

// ---------------- per-dst segment max over y1[src], then relu(max + y2[dst] + b_msg) ----------------
__global__ void k_segmax(const float* __restrict__ bmsg) {
    int w = (blockIdx.x * blockDim.x + threadIdx.x) >> 5;
    int lane = threadIdx.x & 31;
    if (w >= NN) return;
    int beg = g_indptr[w], end = g_indptr[w + 1];
    float4 acc = make_float4(-INFINITY, -INFINITY, -INFINITY, -INFINITY);
    for (int j = beg; j < end; j++) {
        int sv = g_csr_src[j];
        float4 v = *(const float4*)(g_y + (size_t)sv * 256 + lane * 4);
        acc.x = fmaxf(acc.x, v.x); acc.y = fmaxf(acc.y, v.y);
        acc.z = fmaxf(acc.z, v.z); acc.w = fmaxf(acc.w, v.w);
    }
    float4 out;
    if (end > beg) {
        float4 y2 = *(const float4*)(g_y + (size_t)w * 256 + 128 + lane * 4);
        float4 b  = *(const float4*)(bmsg + lane * 4);
        out.x = fmaxf(acc.x + y2.x + b.x, 0.0f);
        out.y = fmaxf(acc.y + y2.y + b.y, 0.0f);
        out.z = fmaxf(acc.z + y2.z + b.z, 0.0f);
        out.w = fmaxf(acc.w + y2.w + b.w, 0.0f);
    } else {
        out = make_float4(0.f, 0.f, 0.f, 0.f);
    }
    *(float4*)(g_agg + (size_t)w * 128 + lane * 4) = out;
}

// ---------------- decoder per-node scalars a1 = h@Wd[:128], a2 = h@Wd[128:] ----------------
__global__ void k_gemv(const float* __restrict__ Wdec) {
    int w = (blockIdx.x * blockDim.x + threadIdx.x) >> 5;
    int lane = threadIdx.x & 31;
    if (w >= NN) return;
    float4 h  = *(const float4*)(g_x + (size_t)w * 256 + 128 + lane * 4);
    float4 u1 = *(const float4*)(Wdec + lane * 4);
    float4 u2 = *(const float4*)(Wdec + 128 + lane * 4);
    float s1 = h.x * u1.x + h.y * u1.y + h.z * u1.z + h.w * u1.w;
    float s2 = h.x * u2.x + h.y * u2.y + h.z * u2.z + h.w * u2.w;
#pragma unroll
    for (int o = 16; o; o >>= 1) {
        s1 += __shfl_down_sync(0xFFFFFFFFu, s1, o);
        s2 += __shfl_down_sync(0xFFFFFFFFu, s2, o);
    }
    if (lane == 0) { g_a1[w] = s1; g_a2[w] = s2; }
}

// ---------------- alpha per edge: preds + incident-max for reach ----------------
__global__ void k_alpha(const int* __restrict__ ei, const float* __restrict__ bdec,
                        float* __restrict__ out, int it) {
    int e = blockIdx.x * blockDim.x + threadIdx.x;
    if (e >= EE) return;
    int sv = ei[e], dv = ei[EE + e];
    float t = g_a1[sv] + g_a2[dv] + bdec[0];
    float al = 1.0f / (1.0f + expf(-t));
    out[(size_t)it * EE + e] = al;
    atomicMax((int*)&g_mx[sv], __float_as_int(al));
    atomicMax((int*)&g_mx[dv], __float_as_int(al));
}

// ---------------- final: reach + parents (argmax incoming alpha, min-eid tiebreak) ----------------
__global__ void k_final(const float* __restrict__ bdec, float* __restrict__ out) {
    int w = (blockIdx.x * blockDim.x + threadIdx.x) >> 5;
    int lane = threadIdx.x & 31;
    if (w >= NN) return;
    if (lane == 0) out[(size_t)10 * EE + w] = (g_mx[w] >= 0.4f) ? 1.0f : 0.0f;
    int beg = g_indptr[w], end = g_indptr[w + 1];
    float bd = bdec[0];
    float a2v = g_a2[w];
    float ba = -1.0f;
    int beid = 0x7FFFFFFF, bsrc = w;
    for (int j = beg + lane; j < end; j += 32) {
        int sv = g_csr_src[j], eid = g_csr_eid[j];
        float t = g_a1[sv] + a2v + bd;
        float al = 1.0f / (1.0f + expf(-t));
        if (al > ba || (al == ba && eid < beid)) { ba = al; beid = eid; bsrc = sv; }
    }
#pragma unroll
    for (int o = 16; o; o >>= 1) {
        float oa = __shfl_xor_sync(0xFFFFFFFFu, ba, o);
        int   oe = __shfl_xor_sync(0xFFFFFFFFu, beid, o);
        int   os = __shfl_xor_sync(0xFFFFFFFFu, bsrc, o);
        if (oa > ba || (oa == ba && oe < beid)) { ba = oa; beid = oe; bsrc = os; }
    }
    if (lane == 0)
        out[(size_t)10 * EE + NN + w] = (float)((end > beg) ? bsrc : w);
}

// ---------------- host ----------------
extern "C" void kernel_launch(void* const* d_in, const int* in_sizes, int n_in,
                              void* d_out, int out_size) {
    const float* pos  = (const float*)d_in[0];
    const float* s    = (const float*)d_in[1];
    const int*   ei   = (const int*)d_in[2];
    const float* Wenc = (const float*)d_in[3];
    const float* benc = (const float*)d_in[4];
    const float* W1   = (const float*)d_in[5];
    const float* W2   = (const float*)d_in[6];
    const float* bmsg = (const float*)d_in[7];
    const float* Wout = (const float*)d_in[8];
    const float* bout = (const float*)d_in[9];
    const float* Wdec = (const float*)d_in[10];
    const float* bdec = (const float*)d_in[11];
    float* out = (float*)d_out;

    float *px = nullptr, *py = nullptr, *pagg = nullptr;
    cudaGetSymbolAddress((void**)&px, g_x);
    cudaGetSymbolAddress((void**)&py, g_y);
    cudaGetSymbolAddress((void**)&pagg, g_agg);

    const int TB = 256;
    k_init<<<(NN * 128 + TB - 1) / TB, TB>>>();
    k_hist<<<(EE + TB - 1) / TB, TB>>>(ei);
    k_scan<<<1, 1024>>>();
    k_scatter<<<(EE + TB - 1) / TB, TB>>>(ei);

    int gemm_rows = (NN + 127) / 128;  // 157
    for (int it = 0; it < ITERS; it++) {
        k_encode<<<(NN * 32 + TB - 1) / TB, TB>>>(pos, s, Wenc, benc, it == 0 ? 1 : 0);
        k_zero_mx<<<(NN + TB - 1) / TB, TB>>>();
        // y = [x@W1 | x@W2]
        k_sgemm<<<dim3(gemm_rows, 2), TB>>>(px, 256, NN, 256, W1, W2, py, 256, nullptr, 0);
        k_segmax<<<(NN + 7) / 8, TB>>>(bmsg);
        // h = relu(agg@Wout + bout) written into x[:,128:256]
        k_sgemm<<<dim3(gemm_rows, 1), TB>>>(pagg, 128, NN, 128, Wout, Wout, px + 128, 256, bout, 1);
        k_gemv<<<(NN + 7) / 8, TB>>>(Wdec);
        k_alpha<<<(EE + TB - 1) / TB, TB>>>(ei, bdec, out, it);
    }
    k_final<<<(NN + 7) / 8, TB>>>(bdec, out);
}

// round 3
// speedup vs baseline: 1.0783x; 1.0783x over previous
#include <cuda_runtime.h>
#include <math.h>
#include <stdint.h>

#define NN 20000
#define EE 320000
#define ITERS 10
#define MBK 157          // number of 128-row M blocks
#define FRAG 16384       // floats of fragment-layout A per (mb): 4 ksteps x 4096

// ---------------- device scratch ----------------
__device__ float g_P0[NN * 256], g_P1[NN * 256], g_y[NN * 256], g_h[NN * 128];
__device__ float g_Ahi[MBK * FRAG], g_Alo[MBK * FRAG];   // h-frag (z-frag during setup)
__device__ float g_Ghi[MBK * FRAG], g_Glo[MBK * FRAG];   // agg-frag
__device__ float g_a1[NN], g_a2[NN], g_mx[NN], g_reach[NN];
__device__ int   g_deg[NN], g_indptr[NN + 1], g_cursor[NN];
__device__ int   g_csr_src[EE], g_csr_eid[EE];
__device__ float g_B1f[2 * 12 * 4096];   // h-rows of [W1|W2], frag layout, K-extended split
__device__ float g_BPf[2 * 12 * 4096];   // z-rows of [W1|W2]
__device__ float g_B2f[12 * 4096];       // Wout

// ---------------- helpers ----------------
__device__ __forceinline__ float tf32_rd(float x) {
    uint32_t r;
    asm("cvt.rna.tf32.f32 %0, %1;" : "=r"(r) : "f"(x));
    return __uint_as_float(r);
}
__device__ __forceinline__ uint32_t smem_u32(const void* p) {
    uint32_t a;
    asm("{ .reg .u64 t; cvta.to.shared.u64 t, %1; cvt.u32.u64 %0, t; }" : "=r"(a) : "l"(p));
    return a;
}
__device__ __forceinline__ void cpasync16(uint32_t dst, const float* src) {
    asm volatile("cp.async.ca.shared.global [%0], [%1], 16;" :: "r"(dst), "l"(src));
}
__device__ __forceinline__ void mma_tf32(float* c, const uint32_t* a, const uint32_t* b) {
    asm volatile(
        "mma.sync.aligned.m16n8k8.row.col.f32.tf32.tf32.f32 "
        "{%0,%1,%2,%3}, {%4,%5,%6,%7}, {%8,%9}, {%0,%1,%2,%3};"
        : "+f"(c[0]), "+f"(c[1]), "+f"(c[2]), "+f"(c[3])
        : "r"(a[0]), "r"(a[1]), "r"(a[2]), "r"(a[3]), "r"(b[0]), "r"(b[1]));
}
// fragment index of A element (row rv in [0,128), col cc in [0,128)) within one mb block
__device__ __forceinline__ int fidx(int rv, int cc) {
    int ks = cc >> 5, kk = (cc >> 3) & 3, mtile = rv >> 4, r = rv & 15;
    return ks * 4096 + (mtile * 4 + kk) * 128 + ((r & 7) * 4 + (cc & 3)) * 4
         + (r >> 3) + (((cc >> 2) & 1) << 1);
}

// ---------------- setup kernels ----------------
__global__ void k_init() {
    int t = blockIdx.x * blockDim.x + threadIdx.x;
    if (t < NN) { g_deg[t] = 0; g_mx[t] = 0.0f; }
}
__global__ void k_hist(const int* __restrict__ ei) {
    int e = blockIdx.x * blockDim.x + threadIdx.x;
    if (e < EE) atomicAdd(&g_deg[ei[EE + e]], 1);
}
__global__ void k_scan() {
    __shared__ int sh[1024];
    int t = threadIdx.x;
    const int CH = 20;
    int base = t * CH, s = 0;
    for (int i = 0; i < CH; i++) { int idx = base + i; if (idx < NN) s += g_deg[idx]; }
    sh[t] = s;
    __syncthreads();
    for (int o = 1; o < 1024; o <<= 1) {
        int v = (t >= o) ? sh[t - o] : 0;
        __syncthreads();
        sh[t] += v;
        __syncthreads();
    }
    int run = (t == 0) ? 0 : sh[t - 1];
    for (int i = 0; i < CH; i++) {
        int idx = base + i;
        if (idx < NN) { g_indptr[idx] = run; g_cursor[idx] = run; run += g_deg[idx]; }
    }
    if (t == 1023) g_indptr[NN] = sh[1023];
}
__global__ void k_scatter(const int* __restrict__ ei) {
    int e = blockIdx.x * blockDim.x + threadIdx.x;
    if (e >= EE) return;
    int d = ei[EE + e];
    int slot = atomicAdd(&g_cursor[d], 1);
    g_csr_src[slot] = ei[e];
    g_csr_eid[slot] = e;
}

// Pack the three B tables directly in fragment layout.
// Layout per table: [cb][ks(12)][ntile(16)][kk(4)][lane(32)][slot(2)]
__global__ void k_prepB(const float* __restrict__ W1, const float* __restrict__ W2,
                        const float* __restrict__ Wout) {
    int t = blockIdx.x * blockDim.x + threadIdx.x;
    int which, rem;
    if (t < 98304) { which = 0; rem = t; }
    else if (t < 196608) { which = 1; rem = t - 98304; }
    else if (t < 245760) { which = 2; rem = t - 196608; }
    else return;
    int cb = rem / 49152;
    int r2 = rem % 49152;
    int ks = r2 >> 12;
    int r3 = r2 & 4095;
    int ntile = r3 >> 8;
    int r4 = r3 & 255;
    int kk = r4 >> 6;
    int r5 = r4 & 63;
    int lane = r5 >> 1, slot = r5 & 1;
    int n = cb * 128 + ntile * 8 + (lane >> 2);
    int ke = ks * 32 + kk * 8 + slot * 4 + (lane & 3);
    int k = ke & 127;
    float v;
    if (which == 0)      v = (n < 128) ? W1[(128 + k) * 128 + n] : W2[(128 + k) * 128 + (n - 128)];
    else if (which == 1) v = (n < 128) ? W1[k * 128 + n] : W2[k * 128 + (n - 128)];
    else                 v = Wout[k * 128 + n];
    float hi = tf32_rd(v);
    float o = (ke < 256) ? hi : tf32_rd(v - hi);
    if (which == 0) g_B1f[rem] = o;
    else if (which == 1) g_BPf[rem] = o;
    else g_B2f[rem] = o;
}

// z(variant) = relu(pos*we0 + rv*we1 + b) -> frag-layout split in g_Ahi/g_Alo
__global__ void k_prepz(const float* __restrict__ pos, const float* __restrict__ Wenc,
                        const float* __restrict__ benc, float rv) {
    int t = blockIdx.x * blockDim.x + threadIdx.x;
    if (t >= NN * 32) return;
    int v = t >> 5, lane = t & 31;
    int c0 = lane << 2;
    float p = pos[v];
    float4 w0 = *(const float4*)(Wenc + c0);
    float4 w1 = *(const float4*)(Wenc + 128 + c0);
    float4 b = *(const float4*)(benc + c0);
    float z[4];
    z[0] = fmaxf(fmaf(p, w0.x, fmaf(rv, w1.x, b.x)), 0.0f);
    z[1] = fmaxf(fmaf(p, w0.y, fmaf(rv, w1.y, b.y)), 0.0f);
    z[2] = fmaxf(fmaf(p, w0.z, fmaf(rv, w1.z, b.z)), 0.0f);
    z[3] = fmaxf(fmaf(p, w0.w, fmaf(rv, w1.w, b.w)), 0.0f);
    int base = (v >> 7) * FRAG;
    int rvb = v & 127;
#pragma unroll
    for (int q = 0; q < 4; q++) {
        float hi = tf32_rd(z[q]);
        float lo = tf32_rd(z[q] - hi);
        int idx = base + fidx(rvb, c0 + q);
        g_Ahi[idx] = hi;
        g_Alo[idx] = lo;
    }
}

// ---------------- mma.sync tf32 split GEMM ----------------
// C[M=NN, NT] over K=384 (hi,hi / lo,hi / hi,lo). modes: 0=store raw P, 1=+P_select->y, 2=relu+bias->h + h-frag
__global__ __launch_bounds__(256, 1) void k_gemm(
    const float* __restrict__ Ahi, const float* __restrict__ Alo,
    const float* __restrict__ Bf, float* __restrict__ Cout, int mode,
    const float* __restrict__ reachp, const float* __restrict__ P0,
    const float* __restrict__ P1, const float* __restrict__ bias,
    float* __restrict__ Hhi, float* __restrict__ Hlo, float* __restrict__ Hrow)
{
    extern __shared__ float smem[];   // [2 bufs][A 4096 | B 4096]
    const int tid = threadIdx.x, lane = tid & 31, wid = tid >> 5;
    const int wm = wid & 1, wn = wid >> 1;
    const int mb = blockIdx.x, cb = blockIdx.y;
    const int row0 = mb * 128;
    const uint32_t sbase = smem_u32(smem);
    const float* Bcb = Bf + cb * 49152;

    float acc[4][4][4];
#pragma unroll
    for (int i = 0; i < 4; i++)
#pragma unroll
        for (int j = 0; j < 4; j++)
#pragma unroll
            for (int q = 0; q < 4; q++) acc[i][j][q] = 0.0f;

    auto stage = [&](int st, int buf) {
        const float* As = (((st >> 2) == 1) ? Alo : Ahi) + mb * FRAG + (st & 3) * 4096;
        const float* Bs = Bcb + st * 4096;
        uint32_t da = sbase + buf * 8192 * 4;
        uint32_t db = da + 4096 * 4;
#pragma unroll
        for (int i = 0; i < 4; i++) {
            int f = tid + 256 * i;
            cpasync16(da + f * 16, As + f * 4);
            cpasync16(db + f * 16, Bs + f * 4);
        }
    };

    stage(0, 0);
    asm volatile("cp.async.commit_group;");

    for (int c = 0; c < 12; c++) {
        int buf = c & 1;
        if (c < 11) {
            stage(c + 1, buf ^ 1);
            asm volatile("cp.async.commit_group;");
            asm volatile("cp.async.wait_group 1;");
        } else {
            asm volatile("cp.async.wait_group 0;");
        }
        __syncthreads();
        const uint4* Ab = (const uint4*)(smem + buf * 8192);
        const uint2* Bb = (const uint2*)(smem + buf * 8192 + 4096);
#pragma unroll
        for (int kk = 0; kk < 4; kk++) {
            uint4 a[4];
            uint2 b[4];
#pragma unroll
            for (int mt = 0; mt < 4; mt++)
                a[mt] = Ab[((wm * 4 + mt) * 4 + kk) * 32 + lane];
#pragma unroll
            for (int nt = 0; nt < 4; nt++)
                b[nt] = Bb[((wn * 4 + nt) * 4 + kk) * 32 + lane];
#pragma unroll
            for (int mt = 0; mt < 4; mt++)
#pragma unroll
                for (int nt = 0; nt < 4; nt++)
                    mma_tf32(acc[mt][nt], (const uint32_t*)&a[mt], (const uint32_t*)&b[nt]);
        }
        __syncthreads();
    }

    // epilogue
    int colofs = cb * 128;
#pragma unroll
    for (int mt = 0; mt < 4; mt++) {
        int rva = wm * 64 + mt * 16 + (lane >> 2);
        int rvb = rva + 8;
        int ga = row0 + rva, gb = row0 + rvb;
        const float *Pa = nullptr, *Pb = nullptr;
        if (mode == 1) {
            if (ga < NN) Pa = (reachp[ga] > 0.5f) ? P1 : P0;
            if (gb < NN) Pb = (reachp[gb] > 0.5f) ? P1 : P0;
        }
#pragma unroll
        for (int nt = 0; nt < 4; nt++) {
            int col = wn * 32 + nt * 8 + ((lane & 3) << 1);
            float c0 = acc[mt][nt][0], c1 = acc[mt][nt][1];
            float c2 = acc[mt][nt][2], c3 = acc[mt][nt][3];
            if (mode == 0) {
                if (ga < NN) { float2 v = {c0, c1}; *(float2*)(Cout + (size_t)ga * 256 + colofs + col) = v; }
                if (gb < NN) { float2 v = {c2, c3}; *(float2*)(Cout + (size_t)gb * 256 + colofs + col) = v; }
            } else if (mode == 1) {
                if (ga < NN) {
                    float2 pv = *(const float2*)(Pa + (size_t)ga * 256 + colofs + col);
                    float2 v = {c0 + pv.x, c1 + pv.y};
                    *(float2*)(Cout + (size_t)ga * 256 + colofs + col) = v;
                }
                if (gb < NN) {
                    float2 pv = *(const float2*)(Pb + (size_t)gb * 256 + colofs + col);
                    float2 v = {c2 + pv.x, c3 + pv.y};
                    *(float2*)(Cout + (size_t)gb * 256 + colofs + col) = v;
                }
            } else {
                float b0 = bias[col], b1 = bias[col + 1];
                if (ga < NN) {
                    float v0 = fmaxf(c0 + b0, 0.0f), v1 = fmaxf(c1 + b1, 0.0f);
                    float2 v = {v0, v1};
                    *(float2*)(Hrow + (size_t)ga * 128 + col) = v;
                    float h0 = tf32_rd(v0), l0 = tf32_rd(v0 - h0);
                    float h1 = tf32_rd(v1), l1 = tf32_rd(v1 - h1);
                    int i0 = mb * FRAG + fidx(rva, col);
                    int i1 = mb * FRAG + fidx(rva, col + 1);
                    Hhi[i0] = h0; Hlo[i0] = l0;
                    Hhi[i1] = h1; Hlo[i1] = l1;
                }
                if (gb < NN) {
                    float v0 = fmaxf(c2 + b0, 0.0f), v1 = fmaxf(c3 + b1, 0.0f);
                    float2 v = {v0, v1};
                    *(float2*)(Hrow + (size_t)gb * 128 + col) = v;
                    float h0 = tf32_rd(v0), l0 = tf32_rd(v0 - h0);
                    float h1 = tf32_rd(v1), l1 = tf32_rd(v1 - h1);
                    int i0 = mb * FRAG + fidx(rvb, col);
                    int i1 = mb * FRAG + fidx(rvb, col + 1);
                    Hhi[i0] = h0; Hlo[i0] = l0;
                    Hhi[i1] = h1; Hlo[i1] = l1;
                }
            }
        }
    }
}

// ---------------- iteration kernels ----------------
// it0: y = P_{s} directly (h == 0)
__global__ void k_ycopy(const float* __restrict__ sflag) {
    int t = blockIdx.x * blockDim.x + threadIdx.x;
    if (t >= NN * 64) return;
    int v = t >> 6, q = (t & 63) * 4;
    const float* P = (sflag[v] > 0.5f) ? g_P1 : g_P0;
    *(float4*)(g_y + (size_t)v * 256 + q) = *(const float4*)(P + (size_t)v * 256 + q);
}

// segment max over y1[src] per dst; relu(max + y2[dst] + b); write agg-frag split
__global__ void k_segmax(const float* __restrict__ bmsg) {
    int w = (blockIdx.x * blockDim.x + threadIdx.x) >> 5;
    int lane = threadIdx.x & 31;
    if (w >= NN) return;
    int beg = g_indptr[w], end = g_indptr[w + 1];
    float4 acc = make_float4(-INFINITY, -INFINITY, -INFINITY, -INFINITY);
    for (int j = beg; j < end; j++) {
        int sv = g_csr_src[j];
        float4 v = *(const float4*)(g_y + (size_t)sv * 256 + lane * 4);
        acc.x = fmaxf(acc.x, v.x); acc.y = fmaxf(acc.y, v.y);
        acc.z = fmaxf(acc.z, v.z); acc.w = fmaxf(acc.w, v.w);
    }
    float o[4];
    if (end > beg) {
        float4 y2 = *(const float4*)(g_y + (size_t)w * 256 + 128 + lane * 4);
        float4 b = *(const float4*)(bmsg + lane * 4);
        o[0] = fmaxf(acc.x + y2.x + b.x, 0.0f);
        o[1] = fmaxf(acc.y + y2.y + b.y, 0.0f);
        o[2] = fmaxf(acc.z + y2.z + b.z, 0.0f);
        o[3] = fmaxf(acc.w + y2.w + b.w, 0.0f);
    } else {
        o[0] = o[1] = o[2] = o[3] = 0.0f;
    }
    int rv = w & 127;
    int mtile = rv >> 4, r = rv & 15;
    int ks = lane >> 3;
    int kk = (lane >> 1) & 3;
    int slotbase = (r >> 3) + ((lane & 1) << 1);
    int base = (w >> 7) * FRAG + ks * 4096 + (mtile * 4 + kk) * 128 + (r & 7) * 16 + slotbase;
#pragma unroll
    for (int q = 0; q < 4; q++) {
        float hi = tf32_rd(o[q]);
        float lo = tf32_rd(o[q] - hi);
        g_Ghi[base + q * 4] = hi;
        g_Glo[base + q * 4] = lo;
    }
}

__global__ void k_gemv(const float* __restrict__ Wdec) {
    int w = (blockIdx.x * blockDim.x + threadIdx.x) >> 5;
    int lane = threadIdx.x & 31;
    if (w >= NN) return;
    float4 h = *(const float4*)(g_h + (size_t)w * 128 + lane * 4);
    float4 u1 = *(const float4*)(Wdec + lane * 4);
    float4 u2 = *(const float4*)(Wdec + 128 + lane * 4);
    float s1 = h.x * u1.x + h.y * u1.y + h.z * u1.z + h.w * u1.w;
    float s2 = h.x * u2.x + h.y * u2.y + h.z * u2.z + h.w * u2.w;
#pragma unroll
    for (int o = 16; o; o >>= 1) {
        s1 += __shfl_down_sync(0xFFFFFFFFu, s1, o);
        s2 += __shfl_down_sync(0xFFFFFFFFu, s2, o);
    }
    if (lane == 0) { g_a1[w] = s1; g_a2[w] = s2; }
}

__global__ void k_alpha(const int* __restrict__ ei, const float* __restrict__ bdec,
                        float* __restrict__ out, int it) {
    int e = blockIdx.x * blockDim.x + threadIdx.x;
    if (e >= EE) return;
    int sv = ei[e], dv = ei[EE + e];
    float t = g_a1[sv] + g_a2[dv] + bdec[0];
    float al = 1.0f / (1.0f + expf(-t));
    out[(size_t)it * EE + e] = al;
    atomicMax((int*)&g_mx[sv], __float_as_int(al));
    atomicMax((int*)&g_mx[dv], __float_as_int(al));
}

__global__ void k_reach() {
    int v = blockIdx.x * blockDim.x + threadIdx.x;
    if (v >= NN) return;
    g_reach[v] = (g_mx[v] >= 0.4f) ? 1.0f : 0.0f;
    g_mx[v] = 0.0f;
}

__global__ void k_final(const float* __restrict__ bdec, float* __restrict__ out) {
    int w = (blockIdx.x * blockDim.x + threadIdx.x) >> 5;
    int lane = threadIdx.x & 31;
    if (w >= NN) return;
    if (lane == 0) out[(size_t)10 * EE + w] = (g_mx[w] >= 0.4f) ? 1.0f : 0.0f;
    int beg = g_indptr[w], end = g_indptr[w + 1];
    float bd = bdec[0];
    float a2v = g_a2[w];
    float ba = -1.0f;
    int beid = 0x7FFFFFFF, bsrc = w;
    for (int j = beg + lane; j < end; j += 32) {
        int sv = g_csr_src[j], eid = g_csr_eid[j];
        float t = g_a1[sv] + a2v + bd;
        float al = 1.0f / (1.0f + expf(-t));
        if (al > ba || (al == ba && eid < beid)) { ba = al; beid = eid; bsrc = sv; }
    }
#pragma unroll
    for (int o = 16; o; o >>= 1) {
        float oa = __shfl_xor_sync(0xFFFFFFFFu, ba, o);
        int oe = __shfl_xor_sync(0xFFFFFFFFu, beid, o);
        int os = __shfl_xor_sync(0xFFFFFFFFu, bsrc, o);
        if (oa > ba || (oa == ba && oe < beid)) { ba = oa; beid = oe; bsrc = os; }
    }
    if (lane == 0)
        out[(size_t)10 * EE + NN + w] = (float)((end > beg) ? bsrc : w);
}

// ---------------- host ----------------
extern "C" void kernel_launch(void* const* d_in, const int* in_sizes, int n_in,
                              void* d_out, int out_size) {
    const float* pos  = (const float*)d_in[0];
    const float* s    = (const float*)d_in[1];
    const int*   ei   = (const int*)d_in[2];
    const float* Wenc = (const float*)d_in[3];
    const float* benc = (const float*)d_in[4];
    const float* W1   = (const float*)d_in[5];
    const float* W2   = (const float*)d_in[6];
    const float* bmsg = (const float*)d_in[7];
    const float* Wout = (const float*)d_in[8];
    const float* bout = (const float*)d_in[9];
    const float* Wdec = (const float*)d_in[10];
    const float* bdec = (const float*)d_in[11];
    float* out = (float*)d_out;

    float *pAhi, *pAlo, *pGhi, *pGlo, *pB1, *pBP, *pB2, *pP0, *pP1, *py, *ph, *preach;
    cudaGetSymbolAddress((void**)&pAhi, g_Ahi);
    cudaGetSymbolAddress((void**)&pAlo, g_Alo);
    cudaGetSymbolAddress((void**)&pGhi, g_Ghi);
    cudaGetSymbolAddress((void**)&pGlo, g_Glo);
    cudaGetSymbolAddress((void**)&pB1, g_B1f);
    cudaGetSymbolAddress((void**)&pBP, g_BPf);
    cudaGetSymbolAddress((void**)&pB2, g_B2f);
    cudaGetSymbolAddress((void**)&pP0, g_P0);
    cudaGetSymbolAddress((void**)&pP1, g_P1);
    cudaGetSymbolAddress((void**)&py, g_y);
    cudaGetSymbolAddress((void**)&ph, g_h);
    cudaGetSymbolAddress((void**)&preach, g_reach);

    const int SMEM = 2 * 8192 * 4;  // 65536
    cudaFuncSetAttribute(k_gemm, cudaFuncAttributeMaxDynamicSharedMemorySize, SMEM);

    const int TB = 256;

    k_init<<<(NN + TB - 1) / TB, TB>>>();
    k_hist<<<(EE + TB - 1) / TB, TB>>>(ei);
    k_scan<<<1, 1024>>>();
    k_scatter<<<(EE + TB - 1) / TB, TB>>>(ei);
    k_prepB<<<(245760 + TB - 1) / TB, TB>>>(W1, W2, Wout);

    // P0, P1 precompute (A = z-frag in g_Ahi/g_Alo)
    k_prepz<<<(NN * 32 + TB - 1) / TB, TB>>>(pos, Wenc, benc, 0.0f);
    k_gemm<<<dim3(MBK, 2), TB, SMEM>>>(pAhi, pAlo, pBP, pP0, 0, nullptr, nullptr, nullptr, nullptr, nullptr, nullptr, nullptr);
    k_prepz<<<(NN * 32 + TB - 1) / TB, TB>>>(pos, Wenc, benc, 1.0f);
    k_gemm<<<dim3(MBK, 2), TB, SMEM>>>(pAhi, pAlo, pBP, pP1, 0, nullptr, nullptr, nullptr, nullptr, nullptr, nullptr, nullptr);

    for (int it = 0; it < ITERS; it++) {
        if (it == 0) {
            k_ycopy<<<(NN * 64 + TB - 1) / TB, TB>>>(s);
        } else {
            k_gemm<<<dim3(MBK, 2), TB, SMEM>>>(pAhi, pAlo, pB1, py, 1, preach, pP0, pP1, nullptr, nullptr, nullptr, nullptr);
        }
        k_segmax<<<(NN + 7) / 8, TB>>>(bmsg);
        k_gemm<<<dim3(MBK, 1), TB, SMEM>>>(pGhi, pGlo, pB2, nullptr, 2, nullptr, nullptr, nullptr, bout, pAhi, pAlo, ph);
        k_gemv<<<(NN + 7) / 8, TB>>>(Wdec);
        k_alpha<<<(EE + TB - 1) / TB, TB>>>(ei, bdec, out, it);
        if (it < ITERS - 1) k_reach<<<(NN + TB - 1) / TB, TB>>>();
    }
    k_final<<<(NN + 7) / 8, TB>>>(bdec, out);
}